// round 13
// baseline (speedup 1.0000x reference)
#include <cuda_runtime.h>
#include <math.h>

#define BB 128
#define NN 512
#define HH 128
#define TT 32
#define G4 512
#define SH 52      // weight hh-rows cached in smem (52 rows, paired into 26 x 16B)
#define REGR 28    // weight hh-rows cached in registers (rows 52..79)
// rows 80..127 streamed from L2 each step

typedef unsigned long long u64;

// ------------------------- device scratch -------------------------
__device__ float  g_te[(size_t)BB * HH * NN];   // tanh(enc_trans): [b][k][n]
__device__ float2 g_Wc[HH * G4];                // [hh][j] = {Wih[j][hh], Whh[j][hh]}
__device__ float  g_W2T[HH * HH];               // [hh][k]
__device__ float  g_W1T[HH * HH];               // [hh][k]
__device__ unsigned g_sub[TT * 2];
__device__ float  g_gum[BB * TT * NN];          // precomputed gumbel noise (8 MB)

// ------------------------- f32x2 packed math (sm_100+) -------------------------
__device__ __forceinline__ u64 f2pack(float x, float y) {
    u64 r; asm("mov.b64 %0,{%1,%2};" : "=l"(r) : "f"(x), "f"(y)); return r;
}
__device__ __forceinline__ void f2unpack(u64 p, float& x, float& y) {
    asm("mov.b64 {%0,%1},%2;" : "=f"(x), "=f"(y) : "l"(p));
}
__device__ __forceinline__ u64 f2fma(u64 a, u64 b, u64 c) {
    u64 d; asm("fma.rn.f32x2 %0,%1,%2,%3;" : "=l"(d) : "l"(a), "l"(b), "l"(c)); return d;
}
__device__ __forceinline__ u64 f2mul(u64 a, u64 b) {
    u64 d; asm("mul.rn.f32x2 %0,%1,%2;" : "=l"(d) : "l"(a), "l"(b)); return d;
}

// ------------------------- Threefry-2x32 (JAX partitionable) -------------------------
__device__ __forceinline__ unsigned rotl32(unsigned x, int r) {
    return (x << r) | (x >> (32 - r));
}
__device__ __forceinline__ void tf2x32(unsigned k0, unsigned k1,
                                       unsigned x0, unsigned x1,
                                       unsigned& o0, unsigned& o1) {
    unsigned ks2 = k0 ^ k1 ^ 0x1BD11BDAu;
    x0 += k0; x1 += k1;
#define TF_RND(r) { x0 += x1; x1 = rotl32(x1, r); x1 ^= x0; }
    TF_RND(13) TF_RND(15) TF_RND(26) TF_RND(6)
    x0 += k1; x1 += ks2 + 1u;
    TF_RND(17) TF_RND(29) TF_RND(16) TF_RND(24)
    x0 += ks2; x1 += k0 + 2u;
    TF_RND(13) TF_RND(15) TF_RND(26) TF_RND(6)
    x0 += k0; x1 += k1 + 3u;
    TF_RND(17) TF_RND(29) TF_RND(16) TF_RND(24)
    x0 += k1; x1 += ks2 + 4u;
    TF_RND(13) TF_RND(15) TF_RND(26) TF_RND(6)
    x0 += ks2; x1 += k0 + 5u;
#undef TF_RND
    o0 = x0; o1 = x1;
}

// ------------------------- prep -------------------------
__global__ void k_prep(const float* __restrict__ W_ih, const float* __restrict__ W_hh,
                       const float* __restrict__ W1,   const float* __restrict__ W2) {
    int tid = blockIdx.x * blockDim.x + threadIdx.x;
    const int NT = 64 * 256;
    for (int i = tid; i < G4 * HH; i += NT) {
        int j = i / HH, hh = i % HH;
        g_Wc[hh * G4 + j] = make_float2(W_ih[i], W_hh[i]);
    }
    for (int i = tid; i < HH * HH; i += NT) {
        int k = i / HH, hh = i % HH;
        g_W2T[hh * HH + k] = W2[i];
        g_W1T[hh * HH + k] = W1[i];
    }
    if (tid == 0) {
        unsigned k0 = 0u, k1 = 42u;   // jax.random.key(42)
        for (int t = 0; t < TT; t++) {
            unsigned a0, a1, b0, b1;
            tf2x32(k0, k1, 0u, 0u, a0, a1);
            tf2x32(k0, k1, 0u, 1u, b0, b1);
            g_sub[2 * t] = b0; g_sub[2 * t + 1] = b1;
            k0 = a0; k1 = a1;
        }
    }
}

// ------------- enc_trans + gumbel table, one dual-role kernel (128 thr/block) -------------
__global__ __launch_bounds__(128) void k_encgum(const float* __restrict__ enc) {
    __shared__ float sAT[HH][36];   // [h][n] (enc role only)
    if (blockIdx.x >= 2048) {
        int bt = blockIdx.x - 2048;          // = b*TT + t
        int t = bt & 31, b = bt >> 5;
        unsigned sk0 = g_sub[2 * t], sk1 = g_sub[2 * t + 1];
        int n0 = threadIdx.x * 4;
        float4 r;
        float* rr = &r.x;
#pragma unroll
        for (int i = 0; i < 4; i++) {
            unsigned o0, o1;
            tf2x32(sk0, sk1, 0u, (unsigned)(b * NN + n0 + i), o0, o1);
            unsigned bits = o0 ^ o1;
            float u = fmaxf(1.17549435e-38f, __uint_as_float((bits >> 9) | 0x3f800000u) - 1.0f);
            rr[i] = -logf(-logf(u));
        }
        ((float4*)g_gum)[(size_t)bt * 128 + threadIdx.x] = r;
        return;
    }

    const int b  = blockIdx.x >> 4;
    const int n0 = (blockIdx.x & 15) * 32;
    {
        const float4* src = (const float4*)(enc + ((size_t)b * NN + n0) * HH);
        for (int i = threadIdx.x; i < 32 * 32; i += 128) {
            int n = i >> 5, h4 = (i & 31) << 2;
            float4 vv = src[i];
            sAT[h4 + 0][n] = vv.x;
            sAT[h4 + 1][n] = vv.y;
            sAT[h4 + 2][n] = vv.z;
            sAT[h4 + 3][n] = vv.w;
        }
    }
    __syncthreads();

    const int k = threadIdx.x;
    u64 acc[16];
    const u64 Z = f2pack(0.f, 0.f);
#pragma unroll
    for (int i = 0; i < 16; i++) acc[i] = Z;

#pragma unroll 4
    for (int h = 0; h < HH; h++) {
        float w = __ldg(&g_W1T[h * HH + k]);
        u64 wd = f2pack(w, w);
        const ulonglong2* row = (const ulonglong2*)&sAT[h][0];
#pragma unroll
        for (int i = 0; i < 8; i++) {
            ulonglong2 q = row[i];
            acc[2 * i]     = f2fma(q.x, wd, acc[2 * i]);
            acc[2 * i + 1] = f2fma(q.y, wd, acc[2 * i + 1]);
        }
    }
    float2* dst = (float2*)(g_te + ((size_t)b * HH + k) * NN + n0);
#pragma unroll
    for (int i = 0; i < 16; i++) {
        float a, bb;
        f2unpack(acc[i], a, bb);
        dst[i] = make_float2(tanhf(a), tanhf(bb));
    }
}

// ------------------------- persistent per-batch decode -------------------------
__global__ __launch_bounds__(512, 1) void k_decode(const float* __restrict__ enc,
                                                   const float* __restrict__ b_ih,
                                                   const float* __restrict__ b_hh,
                                                   const float* __restrict__ v,
                                                   float* __restrict__ out) {
    extern __shared__ ulonglong2 s_wc[];       // [26 * G4] paired weight rows (208 KB)
    __shared__ float2 s_dh[HH];                // {dec, hx}
    __shared__ float  s_cx[HH], s_v[HH];
    __shared__ float2 s_td2[HH];               // {td, td}
    __shared__ float2 s_vtd2[HH];              // {v*td, v*td}
    __shared__ float2 s_v2[HH];                // {v, v}
    __shared__ float  s_score[NN];
    __shared__ float  s_scr[4 * NN];           // scratch (8 KB)
    __shared__ unsigned char s_mask[NN];
    __shared__ float  s_rw[16];
    __shared__ int    s_ri[16];
    __shared__ float  s_rm[16];
    __shared__ float  s_re[16];

    const int b = blockIdx.x;
    const int tid = threadIdx.x;
    const int lane = tid & 31;
    const int wid = tid >> 5;
    const float NEG_INF = __int_as_float(0xff800000);

    // one-time smem weight cache fill: pair rows (2p, 2p+1) into one 16B slot
    for (int i = tid; i < (SH / 2) * G4; i += 512) {
        int p = i >> 9, j = i & 511;
        float2 a = g_Wc[(2 * p) * G4 + j];
        float2 c = g_Wc[(2 * p + 1) * G4 + j];
        ulonglong2 w;
        w.x = *(u64*)&a; w.y = *(u64*)&c;
        s_wc[p * G4 + j] = w;
    }
    // register weight cache: rows SH..SH+REGR-1, this thread's j-column
    u64 rwc[REGR];
#pragma unroll
    for (int i = 0; i < REGR; i++) {
        float2 w = __ldg(&g_Wc[(SH + i) * G4 + tid]);
        rwc[i] = f2pack(w.x, w.y);
    }
    // register W2T cache: in-warp combine layout k = tid>>2, part = tid&3
    const int p3k = tid >> 2, p3p = tid & 3;
    float rw2[32];
#pragma unroll
    for (int i = 0; i < 32; i++)
        rw2[i] = __ldg(&g_W2T[(p3p * 32 + i) * HH + p3k]);

    if (tid < HH) {
        s_cx[tid] = 0.f; s_dh[tid].y = 0.f;
        float vv = v[tid];
        s_v[tid] = vv;
        s_v2[tid] = make_float2(vv, vv);
    }
    s_mask[tid] = 0;

    // dec0 = mean over n of encoder_outputs[b]
    {
        int h = tid & 127, q = tid >> 7;
        const float* p = enc + ((size_t)b * NN + (size_t)q * 128) * HH + h;
        float sum = 0.f;
#pragma unroll 8
        for (int n = 0; n < 128; n++) sum += p[(size_t)n * HH];
        s_scr[tid] = sum;
        __syncthreads();
        if (tid < HH)
            s_dh[tid].x = (s_scr[tid] + s_scr[tid + 128] + s_scr[tid + 256] + s_scr[tid + 384]) * (1.0f / NN);
    }
    __syncthreads();

    const float* teb = g_te + (size_t)b * HH * NN;
    const float bias = b_ih[tid] + b_hh[tid];   // j = tid
    const u64 ONE2 = f2pack(1.f, 1.f);

    for (int t = 0; t < TT; t++) {
        // --- Phase 1: gates[j] via FFMA2; rows: smem(0..51) + regs(52..79) + stream(80..127) ---
        {
            u64 acc2 = f2pack(bias, 0.f);
            const u64* dh64 = (const u64*)s_dh;
            const ulonglong2* dh128 = (const ulonglong2*)s_dh;
#pragma unroll 2
            for (int p = 0; p < SH / 2; p++) {
                ulonglong2 w  = s_wc[p * G4 + tid];
                ulonglong2 dh = dh128[p];
                acc2 = f2fma(dh.x, w.x, acc2);
                acc2 = f2fma(dh.y, w.y, acc2);
            }
#pragma unroll
            for (int i = 0; i < REGR; i++)
                acc2 = f2fma(dh64[SH + i], rwc[i], acc2);
#pragma unroll 8
            for (int hh = SH + REGR; hh < HH; hh++) {
                float2 w = __ldg(&g_Wc[hh * G4 + tid]);
                acc2 = f2fma(dh64[hh], f2pack(w.x, w.y), acc2);
            }
            float ax, ay;
            f2unpack(acc2, ax, ay);
            s_scr[tid] = ax + ay;
        }
        __syncthreads();

        // --- Phase 2: LSTM cell (i,f,g,o) ---
        if (tid < HH) {
            float gi = s_scr[tid];
            float gf = s_scr[HH + tid];
            float gg = s_scr[2 * HH + tid];
            float go = s_scr[3 * HH + tid];
            float si = fmaf(0.5f, tanhf(0.5f * gi), 0.5f);
            float sf = fmaf(0.5f, tanhf(0.5f * gf), 0.5f);
            float tg = tanhf(gg);
            float so = fmaf(0.5f, tanhf(0.5f * go), 0.5f);
            float c  = fmaf(sf, s_cx[tid], si * tg);
            s_cx[tid] = c;
            s_dh[tid].y = so * tanhf(c);
        }
        __syncthreads();

        // --- Phase 3: td[k] = tanh(hx . W2T[:,k]), in-warp combine (validated R12) ---
        {
            float p = 0.f;
#pragma unroll
            for (int i = 0; i < 32; i++)
                p = fmaf(s_dh[p3p * 32 + i].y, rw2[i], p);
            p += __shfl_down_sync(0xffffffffu, p, 2);
            p += __shfl_down_sync(0xffffffffu, p, 1);
            if (p3p == 0) {
                float td = tanhf(p);
                s_td2[p3k]  = make_float2(td, td);
                float vt = s_v[p3k] * td;
                s_vtd2[p3k] = make_float2(vt, vt);
            }
        }
        __syncthreads();

        // --- Phase 4a: rational groups-of-4 + f32x2 ---
        {
            int n4 = tid & 127, q = tid >> 7;
            const float4* tp = reinterpret_cast<const float4*>(teb + (size_t)(q * 32) * NN) + n4;
            float ax = 0.f, ay = 0.f, az = 0.f, aw = 0.f;
#pragma unroll
            for (int g = 0; g < 8; g++) {
                u64 numA = 0ull, denA = ONE2, numB = 0ull, denB = ONE2;
#pragma unroll
                for (int kk = 0; kk < 4; kk++) {
                    int k = q * 32 + g * 4 + kk;
                    float4 te = tp[(size_t)(g * 4 + kk) * (NN / 4)];
                    u64 teA = f2pack(te.x, te.y), teB = f2pack(te.z, te.w);
                    u64 td2 = *(const u64*)&s_td2[k];
                    u64 vt2 = *(const u64*)&s_vtd2[k];
                    u64 vk2 = *(const u64*)&s_v2[k];
                    u64 nkA = f2fma(vk2, teA, vt2);        // v*te + v*td
                    u64 dkA = f2fma(teA, td2, ONE2);       // 1 + te*td
                    numA = f2fma(numA, dkA, f2mul(nkA, denA));
                    denA = f2mul(denA, dkA);
                    u64 nkB = f2fma(vk2, teB, vt2);
                    u64 dkB = f2fma(teB, td2, ONE2);
                    numB = f2fma(numB, dkB, f2mul(nkB, denB));
                    denB = f2mul(denB, dkB);
                }
                float nx, ny, dx, dy;
                f2unpack(numA, nx, ny); f2unpack(denA, dx, dy);
                ax += __fdividef(nx, dx); ay += __fdividef(ny, dy);
                f2unpack(numB, nx, ny); f2unpack(denB, dx, dy);
                az += __fdividef(nx, dx); aw += __fdividef(ny, dy);
            }
            reinterpret_cast<float4*>(s_scr)[q * 128 + n4] = make_float4(ax, ay, az, aw);
        }
        __syncthreads();

        // --- Phase 4b: combine + gumbel + fused online argmax/softmax (validated R12) ---
        {
            float sc = s_scr[tid] + s_scr[NN + tid] + s_scr[2 * NN + tid] + s_scr[3 * NN + tid];
            float gum = __ldg(&g_gum[((size_t)(b * TT + t) << 9) + tid]);

            float sm = s_mask[tid] ? NEG_INF : sc;
            s_score[tid] = sm;
            float mv = sm + gum;
            int   mi = tid;
            float sx = sm;
            float es = s_mask[tid] ? 0.f : 1.f;   // running exp-sum relative to sx
#pragma unroll
            for (int off = 16; off; off >>= 1) {
                float ov = __shfl_down_sync(0xffffffffu, mv, off);
                int   oi = __shfl_down_sync(0xffffffffu, mi, off);
                float ox = __shfl_down_sync(0xffffffffu, sx, off);
                float oe = __shfl_down_sync(0xffffffffu, es, off);
                if (ov > mv || (ov == mv && oi < mi)) { mv = ov; mi = oi; }
                if (ox > sx) { es = oe + es * ((sx == NEG_INF) ? 0.f : expf(sx - ox)); sx = ox; }
                else         { es = es + oe * ((ox == NEG_INF) ? 0.f : expf(ox - sx)); }
            }
            if (lane == 0) { s_rw[wid] = mv; s_ri[wid] = mi; s_rm[wid] = sx; s_re[wid] = es; }
        }
        __syncthreads();

        // --- Final reduce, redundantly in EVERY warp (no publish barrier needed) ---
        int sel;
        {
            float mv = (lane < 16) ? s_rw[lane] : NEG_INF;
            int   mi = (lane < 16) ? s_ri[lane] : 0x7fffffff;
            float sx = (lane < 16) ? s_rm[lane] : NEG_INF;
            float es = (lane < 16) ? s_re[lane] : 0.f;
#pragma unroll
            for (int off = 8; off; off >>= 1) {
                float ov = __shfl_down_sync(0xffffffffu, mv, off);
                int   oi = __shfl_down_sync(0xffffffffu, mi, off);
                float ox = __shfl_down_sync(0xffffffffu, sx, off);
                float oe = __shfl_down_sync(0xffffffffu, es, off);
                if (ov > mv || (ov == mv && oi < mi)) { mv = ov; mi = oi; }
                if (ox > sx) { es = oe + es * ((sx == NEG_INF) ? 0.f : expf(sx - ox)); sx = ox; }
                else         { es = es + oe * ((ox == NEG_INF) ? 0.f : expf(ox - sx)); }
            }
            sel = __shfl_sync(0xffffffffu, mi, 0);
            if (tid == 0) {
                float prob = expf(s_score[mi] - sx) / es;
                out[b * TT + t]           = (float)mi;
                out[BB * TT + b * TT + t] = logf(prob + 1e-9f);
                s_mask[mi] = 1;
            }
        }

        // dec fetch with locally-known sel (no extra barrier before this)
        if (tid < HH)
            s_dh[tid].x = __ldg(enc + ((size_t)b * NN + sel) * HH + tid);
        __syncthreads();
    }
}

// ------------------------- launcher -------------------------
extern "C" void kernel_launch(void* const* d_in, const int* in_sizes, int n_in,
                              void* d_out, int out_size) {
    const float* enc  = (const float*)d_in[0];
    const float* W_ih = (const float*)d_in[1];
    const float* W_hh = (const float*)d_in[2];
    const float* b_ih = (const float*)d_in[3];
    const float* b_hh = (const float*)d_in[4];
    const float* W1   = (const float*)d_in[5];
    const float* W2   = (const float*)d_in[6];
    const float* v    = (const float*)d_in[7];
    (void)in_sizes; (void)n_in; (void)out_size;

    const int smem = (SH / 2) * G4 * sizeof(ulonglong2);   // 212992 bytes
    cudaFuncSetAttribute(k_decode, cudaFuncAttributeMaxDynamicSharedMemorySize, smem);

    k_prep<<<64, 256>>>(W_ih, W_hh, W1, W2);
    k_encgum<<<2048 + BB * TT, 128>>>(enc);
    k_decode<<<BB, 512, smem>>>(enc, b_ih, b_hh, v, (float*)d_out);
}

// round 14
// speedup vs baseline: 1.8792x; 1.8792x over previous
#include <cuda_runtime.h>
#include <math.h>

#define BB 128
#define NN 512
#define HH 128
#define TT 32
#define G4 512
#define SH 52      // weight hh-rows cached in smem (52 rows, paired into 26 x 16B)
#define REGR 28    // weight hh-rows cached in registers (rows 52..79)
// rows 80..127 streamed from L2 each step

typedef unsigned long long u64;

// ------------------------- device scratch -------------------------
__device__ float  g_te[(size_t)BB * HH * NN];   // tanh(enc_trans): [b][k][n]
__device__ float2 g_Wc[HH * G4];                // [hh][j] = {Wih[j][hh], Whh[j][hh]}
__device__ float  g_W2T[HH * HH];               // [hh][k]
__device__ float  g_W1T[HH * HH];               // [hh][k]
__device__ unsigned g_sub[TT * 2];
__device__ float  g_gum[BB * TT * NN];          // precomputed gumbel noise (8 MB)

// ------------------------- f32x2 packed math (sm_100+) -------------------------
__device__ __forceinline__ u64 f2pack(float x, float y) {
    u64 r; asm("mov.b64 %0,{%1,%2};" : "=l"(r) : "f"(x), "f"(y)); return r;
}
__device__ __forceinline__ void f2unpack(u64 p, float& x, float& y) {
    asm("mov.b64 {%0,%1},%2;" : "=f"(x), "=f"(y) : "l"(p));
}
__device__ __forceinline__ u64 f2fma(u64 a, u64 b, u64 c) {
    u64 d; asm("fma.rn.f32x2 %0,%1,%2,%3;" : "=l"(d) : "l"(a), "l"(b), "l"(c)); return d;
}
__device__ __forceinline__ u64 f2mul(u64 a, u64 b) {
    u64 d; asm("mul.rn.f32x2 %0,%1,%2;" : "=l"(d) : "l"(a), "l"(b)); return d;
}

// ------------------------- Threefry-2x32 (JAX partitionable) -------------------------
__device__ __forceinline__ unsigned rotl32(unsigned x, int r) {
    return (x << r) | (x >> (32 - r));
}
__device__ __forceinline__ void tf2x32(unsigned k0, unsigned k1,
                                       unsigned x0, unsigned x1,
                                       unsigned& o0, unsigned& o1) {
    unsigned ks2 = k0 ^ k1 ^ 0x1BD11BDAu;
    x0 += k0; x1 += k1;
#define TF_RND(r) { x0 += x1; x1 = rotl32(x1, r); x1 ^= x0; }
    TF_RND(13) TF_RND(15) TF_RND(26) TF_RND(6)
    x0 += k1; x1 += ks2 + 1u;
    TF_RND(17) TF_RND(29) TF_RND(16) TF_RND(24)
    x0 += ks2; x1 += k0 + 2u;
    TF_RND(13) TF_RND(15) TF_RND(26) TF_RND(6)
    x0 += k0; x1 += k1 + 3u;
    TF_RND(17) TF_RND(29) TF_RND(16) TF_RND(24)
    x0 += k1; x1 += ks2 + 4u;
    TF_RND(13) TF_RND(15) TF_RND(26) TF_RND(6)
    x0 += ks2; x1 += k0 + 5u;
#undef TF_RND
    o0 = x0; o1 = x1;
}

// ------------------------- prep -------------------------
__global__ void k_prep(const float* __restrict__ W_ih, const float* __restrict__ W_hh,
                       const float* __restrict__ W1,   const float* __restrict__ W2) {
    int tid = blockIdx.x * blockDim.x + threadIdx.x;
    const int NT = 64 * 256;
    for (int i = tid; i < G4 * HH; i += NT) {
        int j = i / HH, hh = i % HH;
        g_Wc[hh * G4 + j] = make_float2(W_ih[i], W_hh[i]);
    }
    for (int i = tid; i < HH * HH; i += NT) {
        int k = i / HH, hh = i % HH;
        g_W2T[hh * HH + k] = W2[i];
        g_W1T[hh * HH + k] = W1[i];
    }
    if (tid == 0) {
        unsigned k0 = 0u, k1 = 42u;   // jax.random.key(42)
        for (int t = 0; t < TT; t++) {
            unsigned a0, a1, b0, b1;
            tf2x32(k0, k1, 0u, 0u, a0, a1);
            tf2x32(k0, k1, 0u, 1u, b0, b1);
            g_sub[2 * t] = b0; g_sub[2 * t + 1] = b1;
            k0 = a0; k1 = a1;
        }
    }
}

// ------------- enc_trans + gumbel table, one dual-role kernel (128 thr/block) -------------
__global__ __launch_bounds__(128) void k_encgum(const float* __restrict__ enc) {
    __shared__ float sAT[HH][36];   // [h][n] (enc role only)
    if (blockIdx.x >= 2048) {
        int bt = blockIdx.x - 2048;          // = b*TT + t
        int t = bt & 31, b = bt >> 5;
        unsigned sk0 = g_sub[2 * t], sk1 = g_sub[2 * t + 1];
        int n0 = threadIdx.x * 4;
        float4 r;
        float* rr = &r.x;
#pragma unroll
        for (int i = 0; i < 4; i++) {
            unsigned o0, o1;
            tf2x32(sk0, sk1, 0u, (unsigned)(b * NN + n0 + i), o0, o1);
            unsigned bits = o0 ^ o1;
            float u = fmaxf(1.17549435e-38f, __uint_as_float((bits >> 9) | 0x3f800000u) - 1.0f);
            rr[i] = -logf(-logf(u));
        }
        ((float4*)g_gum)[(size_t)bt * 128 + threadIdx.x] = r;
        return;
    }

    const int b  = blockIdx.x >> 4;
    const int n0 = (blockIdx.x & 15) * 32;
    {
        const float4* src = (const float4*)(enc + ((size_t)b * NN + n0) * HH);
        for (int i = threadIdx.x; i < 32 * 32; i += 128) {
            int n = i >> 5, h4 = (i & 31) << 2;
            float4 vv = src[i];
            sAT[h4 + 0][n] = vv.x;
            sAT[h4 + 1][n] = vv.y;
            sAT[h4 + 2][n] = vv.z;
            sAT[h4 + 3][n] = vv.w;
        }
    }
    __syncthreads();

    const int k = threadIdx.x;
    u64 acc[16];
    const u64 Z = f2pack(0.f, 0.f);
#pragma unroll
    for (int i = 0; i < 16; i++) acc[i] = Z;

#pragma unroll 4
    for (int h = 0; h < HH; h++) {
        float w = __ldg(&g_W1T[h * HH + k]);
        u64 wd = f2pack(w, w);
        const ulonglong2* row = (const ulonglong2*)&sAT[h][0];
#pragma unroll
        for (int i = 0; i < 8; i++) {
            ulonglong2 q = row[i];
            acc[2 * i]     = f2fma(q.x, wd, acc[2 * i]);
            acc[2 * i + 1] = f2fma(q.y, wd, acc[2 * i + 1]);
        }
    }
    float2* dst = (float2*)(g_te + ((size_t)b * HH + k) * NN + n0);
#pragma unroll
    for (int i = 0; i < 16; i++) {
        float a, bb;
        f2unpack(acc[i], a, bb);
        dst[i] = make_float2(tanhf(a), tanhf(bb));
    }
}

// ------------------------- persistent per-batch decode -------------------------
__global__ __launch_bounds__(512, 1) void k_decode(const float* __restrict__ enc,
                                                   const float* __restrict__ b_ih,
                                                   const float* __restrict__ b_hh,
                                                   const float* __restrict__ v,
                                                   float* __restrict__ out) {
    extern __shared__ ulonglong2 s_wc[];       // [26 * G4] paired weight rows (208 KB)
    __shared__ float2 s_dh[HH];                // {dec, hx}
    __shared__ float  s_cx[HH], s_v[HH];
    __shared__ float2 s_td2[HH];               // {td, td}
    __shared__ float2 s_vtd2[HH];              // {v*td, v*td}
    __shared__ float2 s_v2[HH];                // {v, v}
    __shared__ float  s_score[NN];
    __shared__ float  s_scr[4 * NN];           // scratch (8 KB)
    __shared__ unsigned char s_mask[NN];
    __shared__ float  s_rw[16];
    __shared__ int    s_ri[16];
    __shared__ float  s_rm[16];
    __shared__ float  s_re[16];
    __shared__ int    s_sel;

    const int b = blockIdx.x;
    const int tid = threadIdx.x;
    const int lane = tid & 31, wid = tid >> 5;
    const float NEG_INF = __int_as_float(0xff800000);

    // one-time smem weight cache fill: pair rows (2p, 2p+1) into one 16B slot
    for (int i = tid; i < (SH / 2) * G4; i += 512) {
        int p = i >> 9, j = i & 511;
        float2 a = g_Wc[(2 * p) * G4 + j];
        float2 c = g_Wc[(2 * p + 1) * G4 + j];
        ulonglong2 w;
        w.x = *(u64*)&a; w.y = *(u64*)&c;
        s_wc[p * G4 + j] = w;
    }
    // register weight cache: rows SH..SH+REGR-1, this thread's j-column
    u64 rwc[REGR];
#pragma unroll
    for (int i = 0; i < REGR; i++) {
        float2 w = __ldg(&g_Wc[(SH + i) * G4 + tid]);
        rwc[i] = f2pack(w.x, w.y);
    }
    // register W2T cache: this thread's (k, hh-quarter) column, 32 floats
    const int p3k = tid & 127, p3q = tid >> 7;
    float rw2[32];
#pragma unroll
    for (int i = 0; i < 32; i++)
        rw2[i] = __ldg(&g_W2T[(p3q * 32 + i) * HH + p3k]);

    if (tid < HH) {
        s_cx[tid] = 0.f; s_dh[tid].y = 0.f;
        float vv = v[tid];
        s_v[tid] = vv;
        s_v2[tid] = make_float2(vv, vv);
    }
    s_mask[tid] = 0;

    // dec0 = mean over n of encoder_outputs[b]
    {
        int h = tid & 127, q = tid >> 7;
        const float* p = enc + ((size_t)b * NN + (size_t)q * 128) * HH + h;
        float sum = 0.f;
#pragma unroll 8
        for (int n = 0; n < 128; n++) sum += p[(size_t)n * HH];
        s_scr[tid] = sum;
        __syncthreads();
        if (tid < HH)
            s_dh[tid].x = (s_scr[tid] + s_scr[tid + 128] + s_scr[tid + 256] + s_scr[tid + 384]) * (1.0f / NN);
    }
    __syncthreads();

    const float* teb = g_te + (size_t)b * HH * NN;
    const float bias = b_ih[tid] + b_hh[tid];   // j = tid
    const u64 ONE2 = f2pack(1.f, 1.f);

    for (int t = 0; t < TT; t++) {
        // --- Phase 1: gates[j] via FFMA2; rows: smem(0..51) + regs(52..79) + stream(80..127) ---
        {
            u64 acc2 = f2pack(bias, 0.f);
            const u64* dh64 = (const u64*)s_dh;
            const ulonglong2* dh128 = (const ulonglong2*)s_dh;
#pragma unroll 2
            for (int p = 0; p < SH / 2; p++) {
                ulonglong2 w  = s_wc[p * G4 + tid];
                ulonglong2 dh = dh128[p];
                acc2 = f2fma(dh.x, w.x, acc2);
                acc2 = f2fma(dh.y, w.y, acc2);
            }
#pragma unroll
            for (int i = 0; i < REGR; i++)
                acc2 = f2fma(dh64[SH + i], rwc[i], acc2);
#pragma unroll 8
            for (int hh = SH + REGR; hh < HH; hh++) {
                float2 w = __ldg(&g_Wc[hh * G4 + tid]);
                acc2 = f2fma(dh64[hh], f2pack(w.x, w.y), acc2);
            }
            float ax, ay;
            f2unpack(acc2, ax, ay);
            s_scr[tid] = ax + ay;
        }
        __syncthreads();

        // --- Phase 2: LSTM cell (i,f,g,o) ---
        if (tid < HH) {
            float gi = s_scr[tid];
            float gf = s_scr[HH + tid];
            float gg = s_scr[2 * HH + tid];
            float go = s_scr[3 * HH + tid];
            float si = fmaf(0.5f, tanhf(0.5f * gi), 0.5f);
            float sf = fmaf(0.5f, tanhf(0.5f * gf), 0.5f);
            float tg = tanhf(gg);
            float so = fmaf(0.5f, tanhf(0.5f * go), 0.5f);
            float c  = fmaf(sf, s_cx[tid], si * tg);
            s_cx[tid] = c;
            s_dh[tid].y = so * tanhf(c);
        }
        __syncthreads();

        // --- Phase 3: td[k] = tanh(hx . W2T[:,k]) via register-cached W2T ---
        {
            float p = 0.f;
#pragma unroll
            for (int i = 0; i < 32; i++)
                p = fmaf(s_dh[p3q * 32 + i].y, rw2[i], p);
            s_scr[tid] = p;
        }
        __syncthreads();
        if (tid < HH) {
            float td = tanhf(s_scr[tid] + s_scr[tid + 128] + s_scr[tid + 256] + s_scr[tid + 384]);
            s_td2[tid]  = make_float2(td, td);
            float vt = s_v[tid] * td;
            s_vtd2[tid] = make_float2(vt, vt);
        }
        __syncthreads();

        // --- Phase 4a: rational groups-of-4 + f32x2 (gumbel load hoisted to hide latency) ---
        float gum;
        {
            gum = __ldg(&g_gum[((size_t)(b * TT + t) << 9) + tid]);
            int n4 = tid & 127, q = tid >> 7;
            const float4* tp = reinterpret_cast<const float4*>(teb + (size_t)(q * 32) * NN) + n4;
            float ax = 0.f, ay = 0.f, az = 0.f, aw = 0.f;
#pragma unroll
            for (int g = 0; g < 8; g++) {
                u64 numA = 0ull, denA = ONE2, numB = 0ull, denB = ONE2;
#pragma unroll
                for (int kk = 0; kk < 4; kk++) {
                    int k = q * 32 + g * 4 + kk;
                    float4 te = tp[(size_t)(g * 4 + kk) * (NN / 4)];
                    u64 teA = f2pack(te.x, te.y), teB = f2pack(te.z, te.w);
                    u64 td2 = *(const u64*)&s_td2[k];
                    u64 vt2 = *(const u64*)&s_vtd2[k];
                    u64 vk2 = *(const u64*)&s_v2[k];
                    u64 nkA = f2fma(vk2, teA, vt2);        // v*te + v*td
                    u64 dkA = f2fma(teA, td2, ONE2);       // 1 + te*td
                    numA = f2fma(numA, dkA, f2mul(nkA, denA));
                    denA = f2mul(denA, dkA);
                    u64 nkB = f2fma(vk2, teB, vt2);
                    u64 dkB = f2fma(teB, td2, ONE2);
                    numB = f2fma(numB, dkB, f2mul(nkB, denB));
                    denB = f2mul(denB, dkB);
                }
                float nx, ny, dx, dy;
                f2unpack(numA, nx, ny); f2unpack(denA, dx, dy);
                ax += __fdividef(nx, dx); ay += __fdividef(ny, dy);
                f2unpack(numB, nx, ny); f2unpack(denB, dx, dy);
                az += __fdividef(nx, dx); aw += __fdividef(ny, dy);
            }
            reinterpret_cast<float4*>(s_scr)[q * 128 + n4] = make_float4(ax, ay, az, aw);
        }
        __syncthreads();

        // --- Phase 4b: combine + gumbel + fused online argmax/softmax (__expf merges) ---
        {
            float sc = s_scr[tid] + s_scr[NN + tid] + s_scr[2 * NN + tid] + s_scr[3 * NN + tid];

            float sm = s_mask[tid] ? NEG_INF : sc;
            s_score[tid] = sm;
            float mv = sm + gum;
            int   mi = tid;
            float sx = sm;
            float es = s_mask[tid] ? 0.f : 1.f;   // running exp-sum relative to sx
#pragma unroll
            for (int off = 16; off; off >>= 1) {
                float ov = __shfl_down_sync(0xffffffffu, mv, off);
                int   oi = __shfl_down_sync(0xffffffffu, mi, off);
                float ox = __shfl_down_sync(0xffffffffu, sx, off);
                float oe = __shfl_down_sync(0xffffffffu, es, off);
                if (ov > mv || (ov == mv && oi < mi)) { mv = ov; mi = oi; }
                if (ox > sx) { es = oe + es * ((sx == NEG_INF) ? 0.f : __expf(sx - ox)); sx = ox; }
                else         { es = es + oe * ((ox == NEG_INF) ? 0.f : __expf(ox - sx)); }
            }
            if (lane == 0) { s_rw[wid] = mv; s_ri[wid] = mi; s_rm[wid] = sx; s_re[wid] = es; }
        }
        __syncthreads();
        if (wid == 0) {
            float mv = (lane < 16) ? s_rw[lane] : NEG_INF;
            int   mi = (lane < 16) ? s_ri[lane] : 0x7fffffff;
            float sx = (lane < 16) ? s_rm[lane] : NEG_INF;
            float es = (lane < 16) ? s_re[lane] : 0.f;
#pragma unroll
            for (int off = 8; off; off >>= 1) {
                float ov = __shfl_down_sync(0xffffffffu, mv, off);
                int   oi = __shfl_down_sync(0xffffffffu, mi, off);
                float ox = __shfl_down_sync(0xffffffffu, sx, off);
                float oe = __shfl_down_sync(0xffffffffu, es, off);
                if (ov > mv || (ov == mv && oi < mi)) { mv = ov; mi = oi; }
                if (ox > sx) { es = oe + es * ((sx == NEG_INF) ? 0.f : __expf(sx - ox)); sx = ox; }
                else         { es = es + oe * ((ox == NEG_INF) ? 0.f : __expf(ox - sx)); }
            }
            if (lane == 0) {
                float prob = expf(s_score[mi] - sx) / es;
                out[b * TT + t]           = (float)mi;
                out[BB * TT + b * TT + t] = logf(prob + 1e-9f);
                s_mask[mi] = 1;
                s_sel = mi;
            }
        }
        __syncthreads();

        if (tid < HH)
            s_dh[tid].x = __ldg(enc + ((size_t)b * NN + s_sel) * HH + tid);
        __syncthreads();
    }
}

// ------------------------- launcher -------------------------
extern "C" void kernel_launch(void* const* d_in, const int* in_sizes, int n_in,
                              void* d_out, int out_size) {
    const float* enc  = (const float*)d_in[0];
    const float* W_ih = (const float*)d_in[1];
    const float* W_hh = (const float*)d_in[2];
    const float* b_ih = (const float*)d_in[3];
    const float* b_hh = (const float*)d_in[4];
    const float* W1   = (const float*)d_in[5];
    const float* W2   = (const float*)d_in[6];
    const float* v    = (const float*)d_in[7];
    (void)in_sizes; (void)n_in; (void)out_size;

    const int smem = (SH / 2) * G4 * sizeof(ulonglong2);   // 212992 bytes
    cudaFuncSetAttribute(k_decode, cudaFuncAttributeMaxDynamicSharedMemorySize, smem);

    k_prep<<<64, 256>>>(W_ih, W_hh, W1, W2);
    k_encgum<<<2048 + BB * TT, 128>>>(enc);
    k_decode<<<BB, 512, smem>>>(enc, b_ih, b_hh, v, (float*)d_out);
}

// round 15
// speedup vs baseline: 2.0150x; 1.0722x over previous
#include <cuda_runtime.h>
#include <math.h>

#define BB 128
#define NN 512
#define HH 128
#define TT 32
#define G4 512
#define SH 52      // weight hh-rows cached in smem (52 rows, paired into 26 x 16B)
#define REGR 28    // weight hh-rows cached in registers (rows 52..79)
// rows 80..127 streamed from L2 each step

typedef unsigned long long u64;

// ------------------------- device scratch -------------------------
__device__ float  g_te[(size_t)BB * HH * NN];   // tanh(enc_trans): [b][k][n]
__device__ float2 g_Wc[HH * G4];                // [hh][j] = {Wih[j][hh], Whh[j][hh]}
__device__ float  g_W2T[HH * HH];               // [hh][k]
__device__ float  g_W1T[HH * HH];               // [hh][k]
__device__ unsigned g_sub[TT * 2];
__device__ float  g_gum[BB * TT * NN];          // precomputed gumbel noise (8 MB)

// ------------------------- f32x2 packed math (sm_100+) -------------------------
__device__ __forceinline__ u64 f2pack(float x, float y) {
    u64 r; asm("mov.b64 %0,{%1,%2};" : "=l"(r) : "f"(x), "f"(y)); return r;
}
__device__ __forceinline__ void f2unpack(u64 p, float& x, float& y) {
    asm("mov.b64 {%0,%1},%2;" : "=f"(x), "=f"(y) : "l"(p));
}
__device__ __forceinline__ u64 f2fma(u64 a, u64 b, u64 c) {
    u64 d; asm("fma.rn.f32x2 %0,%1,%2,%3;" : "=l"(d) : "l"(a), "l"(b), "l"(c)); return d;
}
__device__ __forceinline__ u64 f2mul(u64 a, u64 b) {
    u64 d; asm("mul.rn.f32x2 %0,%1,%2;" : "=l"(d) : "l"(a), "l"(b)); return d;
}

// ------------------------- Threefry-2x32 (JAX partitionable) -------------------------
__device__ __forceinline__ unsigned rotl32(unsigned x, int r) {
    return (x << r) | (x >> (32 - r));
}
__device__ __forceinline__ void tf2x32(unsigned k0, unsigned k1,
                                       unsigned x0, unsigned x1,
                                       unsigned& o0, unsigned& o1) {
    unsigned ks2 = k0 ^ k1 ^ 0x1BD11BDAu;
    x0 += k0; x1 += k1;
#define TF_RND(r) { x0 += x1; x1 = rotl32(x1, r); x1 ^= x0; }
    TF_RND(13) TF_RND(15) TF_RND(26) TF_RND(6)
    x0 += k1; x1 += ks2 + 1u;
    TF_RND(17) TF_RND(29) TF_RND(16) TF_RND(24)
    x0 += ks2; x1 += k0 + 2u;
    TF_RND(13) TF_RND(15) TF_RND(26) TF_RND(6)
    x0 += k0; x1 += k1 + 3u;
    TF_RND(17) TF_RND(29) TF_RND(16) TF_RND(24)
    x0 += k1; x1 += ks2 + 4u;
    TF_RND(13) TF_RND(15) TF_RND(26) TF_RND(6)
    x0 += ks2; x1 += k0 + 5u;
#undef TF_RND
    o0 = x0; o1 = x1;
}

// ------------------------- prep -------------------------
__global__ void k_prep(const float* __restrict__ W_ih, const float* __restrict__ W_hh,
                       const float* __restrict__ W1,   const float* __restrict__ W2) {
    int tid = blockIdx.x * blockDim.x + threadIdx.x;
    const int NT = 64 * 256;
    for (int i = tid; i < G4 * HH; i += NT) {
        int j = i / HH, hh = i % HH;
        g_Wc[hh * G4 + j] = make_float2(W_ih[i], W_hh[i]);
    }
    for (int i = tid; i < HH * HH; i += NT) {
        int k = i / HH, hh = i % HH;
        g_W2T[hh * HH + k] = W2[i];
        g_W1T[hh * HH + k] = W1[i];
    }
    if (tid == 0) {
        unsigned k0 = 0u, k1 = 42u;   // jax.random.key(42)
        for (int t = 0; t < TT; t++) {
            unsigned a0, a1, b0, b1;
            tf2x32(k0, k1, 0u, 0u, a0, a1);
            tf2x32(k0, k1, 0u, 1u, b0, b1);
            g_sub[2 * t] = b0; g_sub[2 * t + 1] = b1;
            k0 = a0; k1 = a1;
        }
    }
}

// ------------- enc_trans + gumbel table, one dual-role kernel (128 thr/block) -------------
__global__ __launch_bounds__(128) void k_encgum(const float* __restrict__ enc) {
    __shared__ float sAT[HH][36];   // [h][n] (enc role only)
    if (blockIdx.x >= 2048) {
        int bt = blockIdx.x - 2048;          // = b*TT + t
        int t = bt & 31, b = bt >> 5;
        unsigned sk0 = g_sub[2 * t], sk1 = g_sub[2 * t + 1];
        int n0 = threadIdx.x * 4;
        float4 r;
        float* rr = &r.x;
#pragma unroll
        for (int i = 0; i < 4; i++) {
            unsigned o0, o1;
            tf2x32(sk0, sk1, 0u, (unsigned)(b * NN + n0 + i), o0, o1);
            unsigned bits = o0 ^ o1;
            float u = fmaxf(1.17549435e-38f, __uint_as_float((bits >> 9) | 0x3f800000u) - 1.0f);
            rr[i] = -logf(-logf(u));
        }
        ((float4*)g_gum)[(size_t)bt * 128 + threadIdx.x] = r;
        return;
    }

    const int b  = blockIdx.x >> 4;
    const int n0 = (blockIdx.x & 15) * 32;
    {
        const float4* src = (const float4*)(enc + ((size_t)b * NN + n0) * HH);
        for (int i = threadIdx.x; i < 32 * 32; i += 128) {
            int n = i >> 5, h4 = (i & 31) << 2;
            float4 vv = src[i];
            sAT[h4 + 0][n] = vv.x;
            sAT[h4 + 1][n] = vv.y;
            sAT[h4 + 2][n] = vv.z;
            sAT[h4 + 3][n] = vv.w;
        }
    }
    __syncthreads();

    const int k = threadIdx.x;
    u64 acc[16];
    const u64 Z = f2pack(0.f, 0.f);
#pragma unroll
    for (int i = 0; i < 16; i++) acc[i] = Z;

#pragma unroll 4
    for (int h = 0; h < HH; h++) {
        float w = __ldg(&g_W1T[h * HH + k]);
        u64 wd = f2pack(w, w);
        const ulonglong2* row = (const ulonglong2*)&sAT[h][0];
#pragma unroll
        for (int i = 0; i < 8; i++) {
            ulonglong2 q = row[i];
            acc[2 * i]     = f2fma(q.x, wd, acc[2 * i]);
            acc[2 * i + 1] = f2fma(q.y, wd, acc[2 * i + 1]);
        }
    }
    float2* dst = (float2*)(g_te + ((size_t)b * HH + k) * NN + n0);
#pragma unroll
    for (int i = 0; i < 16; i++) {
        float a, bb;
        f2unpack(acc[i], a, bb);
        dst[i] = make_float2(tanhf(a), tanhf(bb));
    }
}

// ------------------------- persistent per-batch decode -------------------------
__global__ __launch_bounds__(512, 1) void k_decode(const float* __restrict__ enc,
                                                   const float* __restrict__ b_ih,
                                                   const float* __restrict__ b_hh,
                                                   const float* __restrict__ v,
                                                   float* __restrict__ out) {
    extern __shared__ ulonglong2 s_wc[];       // [26 * G4] paired weight rows (208 KB)
    __shared__ float2 s_dh[HH];                // {dec, hx}
    __shared__ float  s_cx[HH], s_v[HH];
    __shared__ float2 s_td2[HH];               // {td, td}
    __shared__ float2 s_vtd2[HH];              // {v*td, v*td}
    __shared__ float2 s_v2[HH];                // {v, v}
    __shared__ float  s_score[NN];
    __shared__ float  s_scr[4 * NN];           // scratch (8 KB)
    __shared__ unsigned char s_mask[NN];
    __shared__ float  s_rw[16];
    __shared__ int    s_ri[16];
    __shared__ float  s_re[16];
    __shared__ int    s_sel;

    const int b = blockIdx.x;
    const int tid = threadIdx.x;
    const int lane = tid & 31, wid = tid >> 5;
    const float NEG_INF = __int_as_float(0xff800000);

    // one-time smem weight cache fill: pair rows (2p, 2p+1) into one 16B slot
    for (int i = tid; i < (SH / 2) * G4; i += 512) {
        int p = i >> 9, j = i & 511;
        float2 a = g_Wc[(2 * p) * G4 + j];
        float2 c = g_Wc[(2 * p + 1) * G4 + j];
        ulonglong2 w;
        w.x = *(u64*)&a; w.y = *(u64*)&c;
        s_wc[p * G4 + j] = w;
    }
    // register weight cache: rows SH..SH+REGR-1, this thread's j-column
    u64 rwc[REGR];
#pragma unroll
    for (int i = 0; i < REGR; i++) {
        float2 w = __ldg(&g_Wc[(SH + i) * G4 + tid]);
        rwc[i] = f2pack(w.x, w.y);
    }
    // register W2T cache: in-warp-combine layout k = tid>>2, part = tid&3
    const int p3k = tid >> 2, p3p = tid & 3;
    float rw2[32];
#pragma unroll
    for (int i = 0; i < 32; i++)
        rw2[i] = __ldg(&g_W2T[(p3p * 32 + i) * HH + p3k]);

    if (tid < HH) {
        s_cx[tid] = 0.f; s_dh[tid].y = 0.f;
        float vv = v[tid];
        s_v[tid] = vv;
        s_v2[tid] = make_float2(vv, vv);
    }
    s_mask[tid] = 0;

    // dec0 = mean over n of encoder_outputs[b]
    {
        int h = tid & 127, q = tid >> 7;
        const float* p = enc + ((size_t)b * NN + (size_t)q * 128) * HH + h;
        float sum = 0.f;
#pragma unroll 8
        for (int n = 0; n < 128; n++) sum += p[(size_t)n * HH];
        s_scr[tid] = sum;
        __syncthreads();
        if (tid < HH)
            s_dh[tid].x = (s_scr[tid] + s_scr[tid + 128] + s_scr[tid + 256] + s_scr[tid + 384]) * (1.0f / NN);
    }
    __syncthreads();

    const float* teb = g_te + (size_t)b * HH * NN;
    const float bias = b_ih[tid] + b_hh[tid];   // j = tid
    const u64 ONE2 = f2pack(1.f, 1.f);

    for (int t = 0; t < TT; t++) {
        // --- Phase 1: gates[j] via FFMA2; rows: smem(0..51) + regs(52..79) + stream(80..127) ---
        {
            u64 acc2 = f2pack(bias, 0.f);
            const u64* dh64 = (const u64*)s_dh;
            const ulonglong2* dh128 = (const ulonglong2*)s_dh;
#pragma unroll 2
            for (int p = 0; p < SH / 2; p++) {
                ulonglong2 w  = s_wc[p * G4 + tid];
                ulonglong2 dh = dh128[p];
                acc2 = f2fma(dh.x, w.x, acc2);
                acc2 = f2fma(dh.y, w.y, acc2);
            }
#pragma unroll
            for (int i = 0; i < REGR; i++)
                acc2 = f2fma(dh64[SH + i], rwc[i], acc2);
#pragma unroll 8
            for (int hh = SH + REGR; hh < HH; hh++) {
                float2 w = __ldg(&g_Wc[hh * G4 + tid]);
                acc2 = f2fma(dh64[hh], f2pack(w.x, w.y), acc2);
            }
            float ax, ay;
            f2unpack(acc2, ax, ay);
            s_scr[tid] = ax + ay;
        }
        __syncthreads();

        // --- Phase 2: LSTM cell (i,f,g,o) ---
        if (tid < HH) {
            float gi = s_scr[tid];
            float gf = s_scr[HH + tid];
            float gg = s_scr[2 * HH + tid];
            float go = s_scr[3 * HH + tid];
            float si = fmaf(0.5f, tanhf(0.5f * gi), 0.5f);
            float sf = fmaf(0.5f, tanhf(0.5f * gf), 0.5f);
            float tg = tanhf(gg);
            float so = fmaf(0.5f, tanhf(0.5f * go), 0.5f);
            float c  = fmaf(sf, s_cx[tid], si * tg);
            s_cx[tid] = c;
            s_dh[tid].y = so * tanhf(c);
        }
        __syncthreads();

        // --- Phase 3: td[k] = tanh(hx . W2T[:,k]), in-warp combine (validated R12/R13) ---
        {
            float p = 0.f;
#pragma unroll
            for (int i = 0; i < 32; i++)
                p = fmaf(s_dh[p3p * 32 + i].y, rw2[i], p);
            p += __shfl_down_sync(0xffffffffu, p, 2);
            p += __shfl_down_sync(0xffffffffu, p, 1);
            if (p3p == 0) {
                float td = tanhf(p);
                s_td2[p3k]  = make_float2(td, td);
                float vt = s_v[p3k] * td;
                s_vtd2[p3k] = make_float2(vt, vt);
            }
        }
        __syncthreads();

        // --- Phase 4a: rational groups-of-4 + f32x2 (gumbel load hoisted) ---
        float gum;
        {
            gum = __ldg(&g_gum[((size_t)(b * TT + t) << 9) + tid]);
            int n4 = tid & 127, q = tid >> 7;
            const float4* tp = reinterpret_cast<const float4*>(teb + (size_t)(q * 32) * NN) + n4;
            float ax = 0.f, ay = 0.f, az = 0.f, aw = 0.f;
#pragma unroll
            for (int g = 0; g < 8; g++) {
                u64 numA = 0ull, denA = ONE2, numB = 0ull, denB = ONE2;
#pragma unroll
                for (int kk = 0; kk < 4; kk++) {
                    int k = q * 32 + g * 4 + kk;
                    float4 te = tp[(size_t)(g * 4 + kk) * (NN / 4)];
                    u64 teA = f2pack(te.x, te.y), teB = f2pack(te.z, te.w);
                    u64 td2 = *(const u64*)&s_td2[k];
                    u64 vt2 = *(const u64*)&s_vtd2[k];
                    u64 vk2 = *(const u64*)&s_v2[k];
                    u64 nkA = f2fma(vk2, teA, vt2);        // v*te + v*td
                    u64 dkA = f2fma(teA, td2, ONE2);       // 1 + te*td
                    numA = f2fma(numA, dkA, f2mul(nkA, denA));
                    denA = f2mul(denA, dkA);
                    u64 nkB = f2fma(vk2, teB, vt2);
                    u64 dkB = f2fma(teB, td2, ONE2);
                    numB = f2fma(numB, dkB, f2mul(nkB, denB));
                    denB = f2mul(denB, dkB);
                }
                float nx, ny, dx, dy;
                f2unpack(numA, nx, ny); f2unpack(denA, dx, dy);
                ax += __fdividef(nx, dx); ay += __fdividef(ny, dy);
                f2unpack(numB, nx, ny); f2unpack(denB, dx, dy);
                az += __fdividef(nx, dx); aw += __fdividef(ny, dy);
            }
            reinterpret_cast<float4*>(s_scr)[q * 128 + n4] = make_float4(ax, ay, az, aw);
        }
        __syncthreads();

        // --- Phase 4b: combine + argmax(score+gumbel) + plain-sum denominator ---
        // |score| <= sum|v| ~ 5.1, so exp(score) never overflows: no max-subtraction
        // needed. e is computed ONCE per thread; the shuffle chain carries only
        // (argmax pair, sum) -- no transcendentals in the serial merge.
        {
            float sc = s_scr[tid] + s_scr[NN + tid] + s_scr[2 * NN + tid] + s_scr[3 * NN + tid];

            float sm = s_mask[tid] ? NEG_INF : sc;
            s_score[tid] = sm;
            float e  = __expf(sm);               // 0 for masked lanes
            float mv = sm + gum;
            int   mi = tid;
#pragma unroll
            for (int off = 16; off; off >>= 1) {
                float ov = __shfl_down_sync(0xffffffffu, mv, off);
                int   oi = __shfl_down_sync(0xffffffffu, mi, off);
                float oe = __shfl_down_sync(0xffffffffu, e,  off);
                if (ov > mv || (ov == mv && oi < mi)) { mv = ov; mi = oi; }
                e += oe;
            }
            if (lane == 0) { s_rw[wid] = mv; s_ri[wid] = mi; s_re[wid] = e; }
        }
        __syncthreads();
        if (wid == 0) {
            float mv = (lane < 16) ? s_rw[lane] : NEG_INF;
            int   mi = (lane < 16) ? s_ri[lane] : 0x7fffffff;
            float e  = (lane < 16) ? s_re[lane] : 0.f;
#pragma unroll
            for (int off = 8; off; off >>= 1) {
                float ov = __shfl_down_sync(0xffffffffu, mv, off);
                int   oi = __shfl_down_sync(0xffffffffu, mi, off);
                float oe = __shfl_down_sync(0xffffffffu, e,  off);
                if (ov > mv || (ov == mv && oi < mi)) { mv = ov; mi = oi; }
                e += oe;
            }
            if (lane == 0) {
                float prob = __expf(s_score[mi]) / e;
                out[b * TT + t]           = (float)mi;
                out[BB * TT + b * TT + t] = logf(prob + 1e-9f);
                s_mask[mi] = 1;
                s_sel = mi;
            }
        }
        __syncthreads();

        if (tid < HH)
            s_dh[tid].x = __ldg(enc + ((size_t)b * NN + s_sel) * HH + tid);
        __syncthreads();
    }
}

// ------------------------- launcher -------------------------
extern "C" void kernel_launch(void* const* d_in, const int* in_sizes, int n_in,
                              void* d_out, int out_size) {
    const float* enc  = (const float*)d_in[0];
    const float* W_ih = (const float*)d_in[1];
    const float* W_hh = (const float*)d_in[2];
    const float* b_ih = (const float*)d_in[3];
    const float* b_hh = (const float*)d_in[4];
    const float* W1   = (const float*)d_in[5];
    const float* W2   = (const float*)d_in[6];
    const float* v    = (const float*)d_in[7];
    (void)in_sizes; (void)n_in; (void)out_size;

    const int smem = (SH / 2) * G4 * sizeof(ulonglong2);   // 212992 bytes
    cudaFuncSetAttribute(k_decode, cudaFuncAttributeMaxDynamicSharedMemorySize, smem);

    k_prep<<<64, 256>>>(W_ih, W_hh, W1, W2);
    k_encgum<<<2048 + BB * TT, 128>>>(enc);
    k_decode<<<BB, 512, smem>>>(enc, b_ih, b_hh, v, (float*)d_out);
}

// round 16
// speedup vs baseline: 2.1480x; 1.0660x over previous
#include <cuda_runtime.h>
#include <math.h>

#define BB 128
#define NN 512
#define HH 128
#define TT 32
#define G4 512
#define SH 52      // weight hh-rows cached in smem (52 rows, paired into 26 x 16B)
#define REGR 28    // weight hh-rows cached in registers (rows 52..79)
// rows 80..127 streamed from L2 each step

typedef unsigned long long u64;

// ------------------------- device scratch -------------------------
__device__ float  g_te[(size_t)BB * HH * NN];   // tanh(enc_trans): [b][k][n]
__device__ float2 g_Wc[HH * G4];                // [hh][j] = {Wih[j][hh], Whh[j][hh]}
__device__ float  g_W2T[HH * HH];               // [hh][k]
__device__ float  g_W1T[HH * HH];               // [hh][k]
__device__ unsigned g_sub[TT * 2];
__device__ float  g_gum[BB * TT * NN];          // precomputed gumbel noise (8 MB)

// ------------------------- f32x2 packed math (sm_100+) -------------------------
__device__ __forceinline__ u64 f2pack(float x, float y) {
    u64 r; asm("mov.b64 %0,{%1,%2};" : "=l"(r) : "f"(x), "f"(y)); return r;
}
__device__ __forceinline__ void f2unpack(u64 p, float& x, float& y) {
    asm("mov.b64 {%0,%1},%2;" : "=f"(x), "=f"(y) : "l"(p));
}
__device__ __forceinline__ u64 f2fma(u64 a, u64 b, u64 c) {
    u64 d; asm("fma.rn.f32x2 %0,%1,%2,%3;" : "=l"(d) : "l"(a), "l"(b), "l"(c)); return d;
}
__device__ __forceinline__ u64 f2mul(u64 a, u64 b) {
    u64 d; asm("mul.rn.f32x2 %0,%1,%2;" : "=l"(d) : "l"(a), "l"(b)); return d;
}

// ------------------------- Threefry-2x32 (JAX partitionable) -------------------------
__device__ __forceinline__ unsigned rotl32(unsigned x, int r) {
    return (x << r) | (x >> (32 - r));
}
__device__ __forceinline__ void tf2x32(unsigned k0, unsigned k1,
                                       unsigned x0, unsigned x1,
                                       unsigned& o0, unsigned& o1) {
    unsigned ks2 = k0 ^ k1 ^ 0x1BD11BDAu;
    x0 += k0; x1 += k1;
#define TF_RND(r) { x0 += x1; x1 = rotl32(x1, r); x1 ^= x0; }
    TF_RND(13) TF_RND(15) TF_RND(26) TF_RND(6)
    x0 += k1; x1 += ks2 + 1u;
    TF_RND(17) TF_RND(29) TF_RND(16) TF_RND(24)
    x0 += ks2; x1 += k0 + 2u;
    TF_RND(13) TF_RND(15) TF_RND(26) TF_RND(6)
    x0 += k0; x1 += k1 + 3u;
    TF_RND(17) TF_RND(29) TF_RND(16) TF_RND(24)
    x0 += k1; x1 += ks2 + 4u;
    TF_RND(13) TF_RND(15) TF_RND(26) TF_RND(6)
    x0 += ks2; x1 += k0 + 5u;
#undef TF_RND
    o0 = x0; o1 = x1;
}

// ------------------------- prep -------------------------
__global__ void k_prep(const float* __restrict__ W_ih, const float* __restrict__ W_hh,
                       const float* __restrict__ W1,   const float* __restrict__ W2) {
    int tid = blockIdx.x * blockDim.x + threadIdx.x;
    const int NT = 64 * 256;
    for (int i = tid; i < G4 * HH; i += NT) {
        int j = i / HH, hh = i % HH;
        g_Wc[hh * G4 + j] = make_float2(W_ih[i], W_hh[i]);
    }
    for (int i = tid; i < HH * HH; i += NT) {
        int k = i / HH, hh = i % HH;
        g_W2T[hh * HH + k] = W2[i];
        g_W1T[hh * HH + k] = W1[i];
    }
    if (tid == 0) {
        unsigned k0 = 0u, k1 = 42u;   // jax.random.key(42)
        for (int t = 0; t < TT; t++) {
            unsigned a0, a1, b0, b1;
            tf2x32(k0, k1, 0u, 0u, a0, a1);
            tf2x32(k0, k1, 0u, 1u, b0, b1);
            g_sub[2 * t] = b0; g_sub[2 * t + 1] = b1;
            k0 = a0; k1 = a1;
        }
    }
}

// ------------- enc_trans + gumbel table, one dual-role kernel (128 thr/block) -------------
__global__ __launch_bounds__(128) void k_encgum(const float* __restrict__ enc) {
    __shared__ float sAT[HH][36];   // [h][n] (enc role only)
    if (blockIdx.x >= 2048) {
        int bt = blockIdx.x - 2048;          // = b*TT + t
        int t = bt & 31, b = bt >> 5;
        unsigned sk0 = g_sub[2 * t], sk1 = g_sub[2 * t + 1];
        int n0 = threadIdx.x * 4;
        float4 r;
        float* rr = &r.x;
#pragma unroll
        for (int i = 0; i < 4; i++) {
            unsigned o0, o1;
            tf2x32(sk0, sk1, 0u, (unsigned)(b * NN + n0 + i), o0, o1);
            unsigned bits = o0 ^ o1;
            float u = fmaxf(1.17549435e-38f, __uint_as_float((bits >> 9) | 0x3f800000u) - 1.0f);
            rr[i] = -logf(-logf(u));
        }
        ((float4*)g_gum)[(size_t)bt * 128 + threadIdx.x] = r;
        return;
    }

    const int b  = blockIdx.x >> 4;
    const int n0 = (blockIdx.x & 15) * 32;
    {
        const float4* src = (const float4*)(enc + ((size_t)b * NN + n0) * HH);
        for (int i = threadIdx.x; i < 32 * 32; i += 128) {
            int n = i >> 5, h4 = (i & 31) << 2;
            float4 vv = src[i];
            sAT[h4 + 0][n] = vv.x;
            sAT[h4 + 1][n] = vv.y;
            sAT[h4 + 2][n] = vv.z;
            sAT[h4 + 3][n] = vv.w;
        }
    }
    __syncthreads();

    const int k = threadIdx.x;
    u64 acc[16];
    const u64 Z = f2pack(0.f, 0.f);
#pragma unroll
    for (int i = 0; i < 16; i++) acc[i] = Z;

#pragma unroll 4
    for (int h = 0; h < HH; h++) {
        float w = __ldg(&g_W1T[h * HH + k]);
        u64 wd = f2pack(w, w);
        const ulonglong2* row = (const ulonglong2*)&sAT[h][0];
#pragma unroll
        for (int i = 0; i < 8; i++) {
            ulonglong2 q = row[i];
            acc[2 * i]     = f2fma(q.x, wd, acc[2 * i]);
            acc[2 * i + 1] = f2fma(q.y, wd, acc[2 * i + 1]);
        }
    }
    float2* dst = (float2*)(g_te + ((size_t)b * HH + k) * NN + n0);
#pragma unroll
    for (int i = 0; i < 16; i++) {
        float a, bb;
        f2unpack(acc[i], a, bb);
        dst[i] = make_float2(tanhf(a), tanhf(bb));
    }
}

// ------------------------- persistent per-batch decode -------------------------
__global__ __launch_bounds__(512, 1) void k_decode(const float* __restrict__ enc,
                                                   const float* __restrict__ b_ih,
                                                   const float* __restrict__ b_hh,
                                                   const float* __restrict__ v,
                                                   float* __restrict__ out) {
    extern __shared__ ulonglong2 s_wc[];       // [26 * G4] paired weight rows (208 KB)
    __shared__ float2 s_dh[HH];                // {dec, hx}
    __shared__ float  s_cx[HH], s_v[HH];
    __shared__ float2 s_td2[HH];               // {td, td}
    __shared__ float2 s_vtd2[HH];              // {v*td, v*td}
    __shared__ float2 s_v2[HH];                // {v, v}
    __shared__ float  s_score[NN];
    __shared__ float  s_scr[4 * NN];           // scratch (8 KB)
    __shared__ unsigned char s_mask[NN];
    __shared__ float  s_rw[16];
    __shared__ int    s_ri[16];
    __shared__ float  s_re[16];
    __shared__ int    s_sel;

    const int b = blockIdx.x;
    const int tid = threadIdx.x;
    const int lane = tid & 31, wid = tid >> 5;
    const float NEG_INF = __int_as_float(0xff800000);

    // one-time smem weight cache fill: pair rows (2p, 2p+1) into one 16B slot
    for (int i = tid; i < (SH / 2) * G4; i += 512) {
        int p = i >> 9, j = i & 511;
        float2 a = g_Wc[(2 * p) * G4 + j];
        float2 c = g_Wc[(2 * p + 1) * G4 + j];
        ulonglong2 w;
        w.x = *(u64*)&a; w.y = *(u64*)&c;
        s_wc[p * G4 + j] = w;
    }
    // register weight cache: rows SH..SH+REGR-1, this thread's j-column
    u64 rwc[REGR];
#pragma unroll
    for (int i = 0; i < REGR; i++) {
        float2 w = __ldg(&g_Wc[(SH + i) * G4 + tid]);
        rwc[i] = f2pack(w.x, w.y);
    }
    // register W2T cache: champion broadcast layout k = tid&127, quarter q = tid>>7
    const int p3k = tid & 127, p3q = tid >> 7;
    float rw2[32];
#pragma unroll
    for (int i = 0; i < 32; i++)
        rw2[i] = __ldg(&g_W2T[(p3q * 32 + i) * HH + p3k]);

    if (tid < HH) {
        s_cx[tid] = 0.f; s_dh[tid].y = 0.f;
        float vv = v[tid];
        s_v[tid] = vv;
        s_v2[tid] = make_float2(vv, vv);
    }
    s_mask[tid] = 0;

    // dec0 = mean over n of encoder_outputs[b]
    {
        int h = tid & 127, q = tid >> 7;
        const float* p = enc + ((size_t)b * NN + (size_t)q * 128) * HH + h;
        float sum = 0.f;
#pragma unroll 8
        for (int n = 0; n < 128; n++) sum += p[(size_t)n * HH];
        s_scr[tid] = sum;
        __syncthreads();
        if (tid < HH)
            s_dh[tid].x = (s_scr[tid] + s_scr[tid + 128] + s_scr[tid + 256] + s_scr[tid + 384]) * (1.0f / NN);
    }
    __syncthreads();

    const float* teb = g_te + (size_t)b * HH * NN;
    const float bias = b_ih[tid] + b_hh[tid];   // j = tid
    const u64 ONE2 = f2pack(1.f, 1.f);

    for (int t = 0; t < TT; t++) {
        // --- Phase 1: gates[j] via FFMA2; rows: smem(0..51) + regs(52..79) + stream(80..127) ---
        {
            u64 acc2 = f2pack(bias, 0.f);
            const u64* dh64 = (const u64*)s_dh;
            const ulonglong2* dh128 = (const ulonglong2*)s_dh;
#pragma unroll 2
            for (int p = 0; p < SH / 2; p++) {
                ulonglong2 w  = s_wc[p * G4 + tid];
                ulonglong2 dh = dh128[p];
                acc2 = f2fma(dh.x, w.x, acc2);
                acc2 = f2fma(dh.y, w.y, acc2);
            }
#pragma unroll
            for (int i = 0; i < REGR; i++)
                acc2 = f2fma(dh64[SH + i], rwc[i], acc2);
#pragma unroll 8
            for (int hh = SH + REGR; hh < HH; hh++) {
                float2 w = __ldg(&g_Wc[hh * G4 + tid]);
                acc2 = f2fma(dh64[hh], f2pack(w.x, w.y), acc2);
            }
            float ax, ay;
            f2unpack(acc2, ax, ay);
            s_scr[tid] = ax + ay;
        }
        __syncthreads();

        // --- Phase 2: LSTM cell (i,f,g,o) ---
        if (tid < HH) {
            float gi = s_scr[tid];
            float gf = s_scr[HH + tid];
            float gg = s_scr[2 * HH + tid];
            float go = s_scr[3 * HH + tid];
            float si = fmaf(0.5f, tanhf(0.5f * gi), 0.5f);
            float sf = fmaf(0.5f, tanhf(0.5f * gf), 0.5f);
            float tg = tanhf(gg);
            float so = fmaf(0.5f, tanhf(0.5f * go), 0.5f);
            float c  = fmaf(sf, s_cx[tid], si * tg);
            s_cx[tid] = c;
            s_dh[tid].y = so * tanhf(c);
        }
        __syncthreads();

        // --- Phase 3: td[k] = tanh(hx . W2T[:,k]) via register-cached W2T (broadcast LDS) ---
        {
            float p = 0.f;
#pragma unroll
            for (int i = 0; i < 32; i++)
                p = fmaf(s_dh[p3q * 32 + i].y, rw2[i], p);
            s_scr[tid] = p;
        }
        __syncthreads();
        if (tid < HH) {
            float td = tanhf(s_scr[tid] + s_scr[tid + 128] + s_scr[tid + 256] + s_scr[tid + 384]);
            s_td2[tid]  = make_float2(td, td);
            float vt = s_v[tid] * td;
            s_vtd2[tid] = make_float2(vt, vt);
        }
        __syncthreads();

        // --- Phase 4a: rational groups-of-4 + f32x2 (gumbel load hoisted) ---
        float gum;
        {
            gum = __ldg(&g_gum[((size_t)(b * TT + t) << 9) + tid]);
            int n4 = tid & 127, q = tid >> 7;
            const float4* tp = reinterpret_cast<const float4*>(teb + (size_t)(q * 32) * NN) + n4;
            float ax = 0.f, ay = 0.f, az = 0.f, aw = 0.f;
#pragma unroll
            for (int g = 0; g < 8; g++) {
                u64 numA = 0ull, denA = ONE2, numB = 0ull, denB = ONE2;
#pragma unroll
                for (int kk = 0; kk < 4; kk++) {
                    int k = q * 32 + g * 4 + kk;
                    float4 te = tp[(size_t)(g * 4 + kk) * (NN / 4)];
                    u64 teA = f2pack(te.x, te.y), teB = f2pack(te.z, te.w);
                    u64 td2 = *(const u64*)&s_td2[k];
                    u64 vt2 = *(const u64*)&s_vtd2[k];
                    u64 vk2 = *(const u64*)&s_v2[k];
                    u64 nkA = f2fma(vk2, teA, vt2);        // v*te + v*td
                    u64 dkA = f2fma(teA, td2, ONE2);       // 1 + te*td
                    numA = f2fma(numA, dkA, f2mul(nkA, denA));
                    denA = f2mul(denA, dkA);
                    u64 nkB = f2fma(vk2, teB, vt2);
                    u64 dkB = f2fma(teB, td2, ONE2);
                    numB = f2fma(numB, dkB, f2mul(nkB, denB));
                    denB = f2mul(denB, dkB);
                }
                float nx, ny, dx, dy;
                f2unpack(numA, nx, ny); f2unpack(denA, dx, dy);
                ax += __fdividef(nx, dx); ay += __fdividef(ny, dy);
                f2unpack(numB, nx, ny); f2unpack(denB, dx, dy);
                az += __fdividef(nx, dx); aw += __fdividef(ny, dy);
            }
            reinterpret_cast<float4*>(s_scr)[q * 128 + n4] = make_float4(ax, ay, az, aw);
        }
        __syncthreads();

        // --- Phase 4b: combine + argmax(score+gumbel) + plain-sum denominator ---
        // |score| <= sum|v| ~ 5.1 so exp(score) cannot overflow: no max-subtraction.
        // e computed once per thread BEFORE the tree; merge chain is FADD-only.
        {
            float sc = s_scr[tid] + s_scr[NN + tid] + s_scr[2 * NN + tid] + s_scr[3 * NN + tid];

            float sm = s_mask[tid] ? NEG_INF : sc;
            s_score[tid] = sm;
            float e  = __expf(sm);               // 0 for masked lanes
            float mv = sm + gum;
            int   mi = tid;
#pragma unroll
            for (int off = 16; off; off >>= 1) {
                float ov = __shfl_down_sync(0xffffffffu, mv, off);
                int   oi = __shfl_down_sync(0xffffffffu, mi, off);
                float oe = __shfl_down_sync(0xffffffffu, e,  off);
                if (ov > mv || (ov == mv && oi < mi)) { mv = ov; mi = oi; }
                e += oe;
            }
            if (lane == 0) { s_rw[wid] = mv; s_ri[wid] = mi; s_re[wid] = e; }
        }
        __syncthreads();
        if (wid == 0) {
            float mv = (lane < 16) ? s_rw[lane] : NEG_INF;
            int   mi = (lane < 16) ? s_ri[lane] : 0x7fffffff;
            float e  = (lane < 16) ? s_re[lane] : 0.f;
#pragma unroll
            for (int off = 8; off; off >>= 1) {
                float ov = __shfl_down_sync(0xffffffffu, mv, off);
                int   oi = __shfl_down_sync(0xffffffffu, mi, off);
                float oe = __shfl_down_sync(0xffffffffu, e,  off);
                if (ov > mv || (ov == mv && oi < mi)) { mv = ov; mi = oi; }
                e += oe;
            }
            if (lane == 0) {
                float prob = __expf(s_score[mi]) / e;
                out[b * TT + t]           = (float)mi;
                out[BB * TT + b * TT + t] = logf(prob + 1e-9f);
                s_mask[mi] = 1;
                s_sel = mi;
            }
        }
        __syncthreads();

        if (tid < HH)
            s_dh[tid].x = __ldg(enc + ((size_t)b * NN + s_sel) * HH + tid);
        __syncthreads();
    }
}

// ------------------------- launcher -------------------------
extern "C" void kernel_launch(void* const* d_in, const int* in_sizes, int n_in,
                              void* d_out, int out_size) {
    const float* enc  = (const float*)d_in[0];
    const float* W_ih = (const float*)d_in[1];
    const float* W_hh = (const float*)d_in[2];
    const float* b_ih = (const float*)d_in[3];
    const float* b_hh = (const float*)d_in[4];
    const float* W1   = (const float*)d_in[5];
    const float* W2   = (const float*)d_in[6];
    const float* v    = (const float*)d_in[7];
    (void)in_sizes; (void)n_in; (void)out_size;

    const int smem = (SH / 2) * G4 * sizeof(ulonglong2);   // 212992 bytes
    cudaFuncSetAttribute(k_decode, cudaFuncAttributeMaxDynamicSharedMemorySize, smem);

    k_prep<<<64, 256>>>(W_ih, W_hh, W1, W2);
    k_encgum<<<2048 + BB * TT, 128>>>(enc);
    k_decode<<<BB, 512, smem>>>(enc, b_ih, b_hh, v, (float*)d_out);
}